// round 1
// baseline (speedup 1.0000x reference)
#include <cuda_runtime.h>

#define BQ 8192
#define HDIM 512
#define KNOTS 16
#define HK (HDIM * KNOTS)     // 8192
#define NHB 64                // HK / 128 = number of h-col blocks in kernel2

// Scratch (no cudaMalloc allowed)
__device__ float g_h[BQ * HDIM];        // 16 MB: hidden activations
__device__ float g_ldp[BQ * NHB];       // 2 MB: per-(row, hblock) partial -sum(log p)

__device__ __forceinline__ float fast_tanh(float x) {
    x = fminf(fmaxf(x, -15.f), 15.f);
    float e = __expf(2.f * x);
    return __fdividef(e - 1.f, e + 1.f);
}

// ---------------------------------------------------------------------------
// Kernel 1: g_h = tanh((v_in[:, :512] - 0.5) @ W1 + b1)
// Tile: BM=128 rows x BN=64 cols, KC=16, 256 threads, thread = 4x8 microtile.
// ---------------------------------------------------------------------------
__global__ __launch_bounds__(256) void k_gemm1(
    const float* __restrict__ v_in, const float* __restrict__ W1,
    const float* __restrict__ b1)
{
    __shared__ float  As[16][128];
    __shared__ float4 Bs[16][16];   // 16 x 64 floats

    const int tid  = threadIdx.x;
    const int tc   = tid & 7;       // col octet
    const int tr   = tid >> 3;      // 0..31
    const int row0 = blockIdx.y * 128;
    const int n0   = blockIdx.x * 64;

    float acc[4][8];
#pragma unroll
    for (int r = 0; r < 4; ++r)
#pragma unroll
        for (int c = 0; c < 8; ++c) acc[r][c] = 0.f;

    for (int k0 = 0; k0 < HDIM; k0 += 16) {
        // A tile: 128 rows x 16 k  (512 float4)
#pragma unroll
        for (int i = tid; i < 512; i += 256) {
            int r = i >> 2, kq = i & 3;
            float4 v = *(const float4*)&v_in[(size_t)(row0 + r) * (2 * HDIM) + k0 + kq * 4];
            As[kq * 4 + 0][r] = v.x - 0.5f;
            As[kq * 4 + 1][r] = v.y - 0.5f;
            As[kq * 4 + 2][r] = v.z - 0.5f;
            As[kq * 4 + 3][r] = v.w - 0.5f;
        }
        // B tile: 16 k x 64 cols (256 float4)
        {
            int i = tid;
            if (i < 256) {
                int k = i >> 4, nq = i & 15;
                Bs[k][nq] = *(const float4*)&W1[(size_t)(k0 + k) * HDIM + n0 + nq * 4];
            }
        }
        __syncthreads();

#pragma unroll
        for (int k = 0; k < 16; ++k) {
            float av[4];
#pragma unroll
            for (int r = 0; r < 4; ++r) av[r] = As[k][tr + 32 * r];
            float4 bA = Bs[k][tc * 2 + 0];
            float4 bB = Bs[k][tc * 2 + 1];
            float bv[8] = {bA.x, bA.y, bA.z, bA.w, bB.x, bB.y, bB.z, bB.w};
#pragma unroll
            for (int r = 0; r < 4; ++r)
#pragma unroll
                for (int c = 0; c < 8; ++c) acc[r][c] += av[r] * bv[c];
        }
        __syncthreads();
    }

    float bb[8];
#pragma unroll
    for (int c = 0; c < 8; ++c) bb[c] = b1[n0 + tc * 8 + c];

#pragma unroll
    for (int r = 0; r < 4; ++r) {
        int row = row0 + tr + 32 * r;
#pragma unroll
        for (int c = 0; c < 8; ++c) {
            g_h[(size_t)row * HDIM + n0 + tc * 8 + c] = fast_tanh(acc[r][c] + bb[c]);
        }
    }
}

// ---------------------------------------------------------------------------
// Kernel 2 (dominant): fused GEMM2 + tanh + softmax(K=16) + spline + logp.
// Tile: BM=128 rows x BN=128 cols (8 h-groups), KC=16, 256 threads.
// Thread = 4 rows x 1 full group (16 cols) -> 64 accumulators.
// ---------------------------------------------------------------------------
__global__ __launch_bounds__(256) void k_gemm2_fused(
    const float* __restrict__ v_in, const float* __restrict__ W2,
    const float* __restrict__ b2, float* __restrict__ dout)
{
    __shared__ float  As[16][128];
    __shared__ float4 Bs[16][32];   // 16 x 128 floats
    __shared__ float  red[128][8];

    const int tid  = threadIdx.x;
    const int tg   = tid & 7;       // group within block (0..7)
    const int tq   = tid >> 3;      // 0..31
    const int n0   = blockIdx.x * 128;   // column base in HK
    const int row0 = blockIdx.y * 128;

    float acc[4][16];
#pragma unroll
    for (int r = 0; r < 4; ++r)
#pragma unroll
        for (int j = 0; j < 16; ++j) acc[r][j] = 0.f;

    for (int k0 = 0; k0 < HDIM; k0 += 16) {
        // A tile from g_h: 128 rows x 16 k
#pragma unroll
        for (int i = tid; i < 512; i += 256) {
            int r = i >> 2, kq = i & 3;
            float4 v = *(const float4*)&g_h[(size_t)(row0 + r) * HDIM + k0 + kq * 4];
            As[kq * 4 + 0][r] = v.x;
            As[kq * 4 + 1][r] = v.y;
            As[kq * 4 + 2][r] = v.z;
            As[kq * 4 + 3][r] = v.w;
        }
        // B tile from W2: 16 k x 128 cols (512 float4)
#pragma unroll
        for (int i = tid; i < 512; i += 256) {
            int k = i >> 5, nq = i & 31;
            Bs[k][nq] = *(const float4*)&W2[(size_t)(k0 + k) * HK + n0 + nq * 4];
        }
        __syncthreads();

#pragma unroll
        for (int k = 0; k < 16; ++k) {
            float av[4];
#pragma unroll
            for (int r = 0; r < 4; ++r) av[r] = As[k][tq + 32 * r];
            float4 b0 = Bs[k][tg * 4 + 0];
            float4 b1v = Bs[k][tg * 4 + 1];
            float4 b2v = Bs[k][tg * 4 + 2];
            float4 b3v = Bs[k][tg * 4 + 3];
            float bv[16] = {b0.x, b0.y, b0.z, b0.w, b1v.x, b1v.y, b1v.z, b1v.w,
                            b2v.x, b2v.y, b2v.z, b2v.w, b3v.x, b3v.y, b3v.z, b3v.w};
#pragma unroll
            for (int r = 0; r < 4; ++r)
#pragma unroll
                for (int j = 0; j < 16; ++j) acc[r][j] += av[r] * bv[j];
        }
        __syncthreads();
    }

    // Epilogue: tanh -> softmax over j -> spline eval -> -log p_k
    float bb[16];
#pragma unroll
    for (int j = 0; j < 16; ++j) bb[j] = b2[n0 + tg * 16 + j];

    const int h = (n0 >> 4) + tg;   // global hidden index of this group

#pragma unroll
    for (int r = 0; r < 4; ++r) {
        const int row = row0 + tq + 32 * r;
        float e[16];
        float sum = 0.f;
#pragma unroll
        for (int j = 0; j < 16; ++j) {
            float t = fast_tanh(acc[r][j] + bb[j]);
            e[j] = __expf(t);
            sum += e[j];
        }
        float v = v_in[(size_t)row * (2 * HDIM) + HDIM + h];
        int kk = (int)(v * 16.f);
        kk = kk < 0 ? 0 : (kk > 15 ? 15 : kk);
        float pref = 0.f, pk = 0.f;
#pragma unroll
        for (int j = 0; j < 16; ++j) {
            if (j < kk)  pref += e[j];
            if (j == kk) pk = e[j];
        }
        float inv   = __fdividef(1.f, sum);
        float p_k   = pk * inv;
        float y_lo  = pref * inv;
        float alpha = v * 16.f - (float)kk;
        dout[(size_t)row * (2 * HDIM) + HDIM + h] = y_lo + alpha * p_k;
        red[tq + 32 * r][tg] = -__logf(p_k);
    }
    __syncthreads();

    // Deterministic fixed-order reduction of the 8 groups per row
    if (tid < 128) {
        float s = 0.f;
#pragma unroll
        for (int g = 0; g < 8; ++g) s += red[tid][g];
        g_ldp[(size_t)(row0 + tid) * NHB + blockIdx.x] = s;
    }
}

// ---------------------------------------------------------------------------
// Kernel 3: copy v_passive into out[:, :512]
// ---------------------------------------------------------------------------
__global__ __launch_bounds__(256) void k_copy_passive(
    const float* __restrict__ v_in, float* __restrict__ dout)
{
    int i = blockIdx.x * blockDim.x + threadIdx.x;   // float4 index over B*128
    if (i < BQ * 128) {
        int row = i >> 7, c4 = i & 127;
        const float4* src = (const float4*)v_in;
        float4* dst = (float4*)dout;
        dst[(size_t)row * 256 + c4] = src[(size_t)row * 256 + c4];
    }
}

// ---------------------------------------------------------------------------
// Kernel 4: log_density_out[b] = log_density[b] + sum_hb g_ldp[b][hb]
// ---------------------------------------------------------------------------
__global__ __launch_bounds__(256) void k_finalize_ld(
    const float* __restrict__ log_density, float* __restrict__ dout)
{
    int b = blockIdx.x * blockDim.x + threadIdx.x;
    if (b < BQ) {
        float s = log_density[b];
        const float4* p = (const float4*)&g_ldp[(size_t)b * NHB];
#pragma unroll
        for (int i = 0; i < NHB / 4; ++i) {
            float4 v = p[i];
            s += v.x + v.y + v.z + v.w;
        }
        dout[(size_t)BQ * (2 * HDIM) + b] = s;
    }
}

extern "C" void kernel_launch(void* const* d_in, const int* in_sizes, int n_in,
                              void* d_out, int out_size)
{
    const float* v_in  = (const float*)d_in[0];   // [8192, 1024]
    const float* logd  = (const float*)d_in[1];   // [8192, 1]
    const float* W1    = (const float*)d_in[2];   // [512, 512]
    const float* b1    = (const float*)d_in[3];   // [512]
    const float* W2    = (const float*)d_in[4];   // [512, 8192]
    const float* b2    = (const float*)d_in[5];   // [8192]
    float* out = (float*)d_out;                   // [8192*1024 + 8192]

    k_copy_passive<<<(BQ * 128 + 255) / 256, 256>>>(v_in, out);
    k_gemm1<<<dim3(HDIM / 64, BQ / 128), 256>>>(v_in, W1, b1);
    k_gemm2_fused<<<dim3(HK / 128, BQ / 128), 256>>>(v_in, W2, b2, out);
    k_finalize_ld<<<BQ / 256, 256>>>(logd, out);
}

// round 3
// speedup vs baseline: 6.9772x; 6.9772x over previous
#include <cuda_runtime.h>
#include <cuda_bf16.h>
#include <cstdint>

#define BQ 8192
#define HDIM 512
#define HK 8192
#define NT2 64               // gemm2 n-tiles = 8192/128
#define NC 24                // k-chunks: 3 segments x (512/64)
#define STAGE_BYTES 32768    // A 16KB + B 16KB
#define SMEM_RED 98304       // 3 stages
#define DYNSMEM 102400

// ---------------- device scratch (no cudaMalloc allowed) -------------------
__device__ __align__(16) __nv_bfloat16 g_a1h[BQ*HDIM];
__device__ __align__(16) __nv_bfloat16 g_a1l[BQ*HDIM];
__device__ __align__(16) __nv_bfloat16 g_hh [BQ*HDIM];
__device__ __align__(16) __nv_bfloat16 g_hl [BQ*HDIM];
__device__ __align__(16) __nv_bfloat16 g_w1h[HDIM*HDIM];
__device__ __align__(16) __nv_bfloat16 g_w1l[HDIM*HDIM];
__device__ __align__(16) __nv_bfloat16 g_w2h[(size_t)HK*HDIM];
__device__ __align__(16) __nv_bfloat16 g_w2l[(size_t)HK*HDIM];
__device__ float g_ldp[(size_t)BQ*NT2];

// ---------------- helpers ---------------------------------------------------
__device__ __forceinline__ uint32_t smem_u32(const void* p){
    uint32_t a;
    asm("{ .reg .u64 t; cvta.to.shared.u64 t, %1; cvt.u32.u64 %0, t; }" : "=r"(a) : "l"(p));
    return a;
}
__device__ __forceinline__ void cp16(uint32_t dst, const void* src){
    asm volatile("cp.async.cg.shared.global [%0], [%1], 16;" :: "r"(dst), "l"(src));
}
__device__ __forceinline__ void cp_commit(){
    asm volatile("cp.async.commit_group;" ::: "memory");
}
template<int N> __device__ __forceinline__ void cp_wait(){
    asm volatile("cp.async.wait_group %0;" :: "n"(N) : "memory");
}
__device__ __forceinline__ void ldsm4(uint32_t* r, uint32_t addr){
    asm volatile("ldmatrix.sync.aligned.m8n8.x4.shared.b16 {%0,%1,%2,%3}, [%4];"
        : "=r"(r[0]), "=r"(r[1]), "=r"(r[2]), "=r"(r[3]) : "r"(addr));
}
__device__ __forceinline__ void mma16816(float* d, const uint32_t* a, const uint32_t* b){
    asm volatile("mma.sync.aligned.m16n8k16.row.col.f32.bf16.bf16.f32 "
        "{%0,%1,%2,%3},{%4,%5,%6,%7},{%8,%9},{%0,%1,%2,%3};"
        : "+f"(d[0]), "+f"(d[1]), "+f"(d[2]), "+f"(d[3])
        : "r"(a[0]), "r"(a[1]), "r"(a[2]), "r"(a[3]), "r"(b[0]), "r"(b[1]));
}
__device__ __forceinline__ float fast_tanh(float x){
    x = fminf(fmaxf(x, -15.f), 15.f);
    float e = __expf(2.f * x);
    return __fdividef(e - 1.f, e + 1.f);
}

// ---------------- mainloop --------------------------------------------------
// A: [rows, 512] bf16 hi/lo (k contiguous). B: Wt [Ntot, 512] bf16 hi/lo.
// Result C[128][128] fp32 staged into smem at Csmem (stride 132).
__device__ __forceinline__ void issue_chunk(
    int c, uint32_t sbase,
    const __nv_bfloat16* __restrict__ ah, const __nv_bfloat16* __restrict__ al,
    const __nv_bfloat16* __restrict__ bh, const __nv_bfloat16* __restrict__ bl,
    int row0, int n0, int tid)
{
    const int seg = c >> 3;
    const int kk  = (c & 7) << 6;
    const __nv_bfloat16* a = (seg == 1) ? al : ah;
    const __nv_bfloat16* b = (seg == 2) ? bl : bh;
    uint32_t abase = sbase, bbase = sbase + 16384;
#pragma unroll
    for (int j = 0; j < 4; ++j) {                // A: 128 rows x 128B
        int i = tid + 256 * j;
        int r = i >> 3, q = i & 7;
        uint32_t sw = (uint32_t)(r * 128) + ((uint32_t)(q ^ (r & 7)) << 4);
        cp16(abase + sw, a + (size_t)(row0 + r) * HDIM + kk + q * 8);
    }
#pragma unroll
    for (int j = 0; j < 4; ++j) {                // B: 128 n-rows x 128B
        int i = tid + 256 * j;
        int r = i >> 3, q = i & 7;
        uint32_t sw = (uint32_t)(r * 128) + ((uint32_t)(q ^ (r & 7)) << 4);
        cp16(bbase + sw, b + (size_t)(n0 + r) * HDIM + kk + q * 8);
    }
    cp_commit();
}

__device__ __forceinline__ void gemm_mainloop(
    const __nv_bfloat16* ah, const __nv_bfloat16* al,
    const __nv_bfloat16* bh, const __nv_bfloat16* bl,
    int row0, int n0, char* dsm, float* Csmem)
{
    const int tid  = threadIdx.x;
    const int wid  = tid >> 5;
    const int lane = tid & 31;
    const int wm   = wid & 1;          // 0/1 -> 64-row half
    const int wn   = wid >> 1;         // 0..3 -> 32-col quarter
    const uint32_t sb = smem_u32(dsm);

    float acc[4][4][4];
#pragma unroll
    for (int mi = 0; mi < 4; ++mi)
#pragma unroll
        for (int ni = 0; ni < 4; ++ni)
#pragma unroll
            for (int q = 0; q < 4; ++q) acc[mi][ni][q] = 0.f;

    // lane-invariant pieces of ldmatrix addressing
    const int arow = wm * 64 + (lane & 15);           // + mi*16
    const int ahl  = lane >> 4;                       // A k-half
    const int brow = wn * 32 + (lane & 7) + ((lane >> 4) << 3);  // + bi*16
    const int bhl  = (lane >> 3) & 1;                 // B k-half

    issue_chunk(0, sb,               ah, al, bh, bl, row0, n0, tid);
    issue_chunk(1, sb + STAGE_BYTES, ah, al, bh, bl, row0, n0, tid);

    for (int i = 0; i < NC; ++i) {
        if (i + 2 < NC) {
            issue_chunk(i + 2, sb + (uint32_t)((i + 2) % 3) * STAGE_BYTES,
                        ah, al, bh, bl, row0, n0, tid);
            cp_wait<2>();
        } else {
            cp_wait<0>();
        }
        __syncthreads();

        uint32_t ab = sb + (uint32_t)(i % 3) * STAGE_BYTES;
        uint32_t bb = ab + 16384;
#pragma unroll
        for (int ks = 0; ks < 4; ++ks) {
            uint32_t af[4][4], bf[2][4];
#pragma unroll
            for (int mi = 0; mi < 4; ++mi) {
                int r = arow + mi * 16;
                uint32_t addr = ab + (uint32_t)(r * 128)
                              + ((uint32_t)((ks * 2 + ahl) ^ (r & 7)) << 4);
                ldsm4(af[mi], addr);
            }
#pragma unroll
            for (int bi = 0; bi < 2; ++bi) {
                int r = brow + bi * 16;
                uint32_t addr = bb + (uint32_t)(r * 128)
                              + ((uint32_t)((ks * 2 + bhl) ^ (r & 7)) << 4);
                ldsm4(bf[bi], addr);
            }
#pragma unroll
            for (int mi = 0; mi < 4; ++mi)
#pragma unroll
                for (int ni = 0; ni < 4; ++ni)
                    mma16816(acc[mi][ni], af[mi], &bf[ni >> 1][(ni & 1) * 2]);
        }
        __syncthreads();
    }

    // stage C to smem (aliases stage buffers; all compute done + barrier above)
    const int gid = lane >> 2;
    const int c0  = wn * 32 + (lane & 3) * 2;
#pragma unroll
    for (int mi = 0; mi < 4; ++mi) {
        int r = wm * 64 + mi * 16 + gid;
#pragma unroll
        for (int ni = 0; ni < 4; ++ni) {
            float2 lo = make_float2(acc[mi][ni][0], acc[mi][ni][1]);
            float2 hi = make_float2(acc[mi][ni][2], acc[mi][ni][3]);
            *(float2*)&Csmem[(size_t)r * 132 + c0 + ni * 8]       = lo;
            *(float2*)&Csmem[(size_t)(r + 8) * 132 + c0 + ni * 8] = hi;
        }
    }
    __syncthreads();
}

// ---------------- GEMM1: h = tanh((v_p-0.5)@W1+b1) -> bf16 hi/lo ------------
__global__ __launch_bounds__(256, 2) void k_gemm1_tc(const float* __restrict__ b1)
{
    extern __shared__ char dsm[];
    float* Csmem = (float*)dsm;
    const int row0 = blockIdx.y * 128;
    const int n0   = blockIdx.x * 128;

    gemm_mainloop(g_a1h, g_a1l, g_w1h, g_w1l, row0, n0, dsm, Csmem);

    const int tid = threadIdx.x;
    const int r   = tid >> 1;
    const int ch  = (tid & 1) * 64;
    const int row = row0 + r;
#pragma unroll 4
    for (int c = 0; c < 64; c += 4) {
        float4 v = *(float4*)&Csmem[(size_t)r * 132 + ch + c];
        int cg = n0 + ch + c;
        float t0 = fast_tanh(v.x + b1[cg + 0]);
        float t1 = fast_tanh(v.y + b1[cg + 1]);
        float t2 = fast_tanh(v.z + b1[cg + 2]);
        float t3 = fast_tanh(v.w + b1[cg + 3]);
        __nv_bfloat16 h0 = __float2bfloat16(t0), h1 = __float2bfloat16(t1);
        __nv_bfloat16 h2 = __float2bfloat16(t2), h3 = __float2bfloat16(t3);
        __nv_bfloat162 ha; ha.x = h0; ha.y = h1;
        __nv_bfloat162 hb; hb.x = h2; hb.y = h3;
        __nv_bfloat162 la, lb;
        la.x = __float2bfloat16(t0 - __bfloat162float(h0));
        la.y = __float2bfloat16(t1 - __bfloat162float(h1));
        lb.x = __float2bfloat16(t2 - __bfloat162float(h2));
        lb.y = __float2bfloat16(t3 - __bfloat162float(h3));
        *(__nv_bfloat162*)&g_hh[(size_t)row * HDIM + cg]     = ha;
        *(__nv_bfloat162*)&g_hh[(size_t)row * HDIM + cg + 2] = hb;
        *(__nv_bfloat162*)&g_hl[(size_t)row * HDIM + cg]     = la;
        *(__nv_bfloat162*)&g_hl[(size_t)row * HDIM + cg + 2] = lb;
    }
}

// ---------------- GEMM2 fused: tanh->softmax(16)->spline->logp --------------
__global__ __launch_bounds__(256, 2) void k_gemm2_tc(
    const float* __restrict__ v_in, const float* __restrict__ b2,
    float* __restrict__ dout)
{
    extern __shared__ char dsm[];
    float* Csmem = (float*)dsm;
    float* red   = (float*)(dsm + SMEM_RED);        // [128][8]
    const int row0 = blockIdx.y * 128;
    const int n0   = blockIdx.x * 128;
    const int hbase = n0 >> 4;                      // 8 h per tile

    gemm_mainloop(g_hh, g_hl, g_w2h, g_w2l, row0, n0, dsm, Csmem);

    const int tid = threadIdx.x;
#pragma unroll 1
    for (int p = 0; p < 4; ++p) {
        int idx = p * 256 + tid;          // 1024 (row, group) pairs
        int r = idx >> 3, g = idx & 7;
        float e[16]; float sum = 0.f;
        const float* crow = &Csmem[(size_t)r * 132 + g * 16];
#pragma unroll
        for (int j4 = 0; j4 < 4; ++j4) {
            float4 cv = *(const float4*)&crow[j4 * 4];
            float t0 = fast_tanh(cv.x + b2[n0 + g * 16 + j4 * 4 + 0]);
            float t1 = fast_tanh(cv.y + b2[n0 + g * 16 + j4 * 4 + 1]);
            float t2 = fast_tanh(cv.z + b2[n0 + g * 16 + j4 * 4 + 2]);
            float t3 = fast_tanh(cv.w + b2[n0 + g * 16 + j4 * 4 + 3]);
            e[j4*4+0] = __expf(t0); e[j4*4+1] = __expf(t1);
            e[j4*4+2] = __expf(t2); e[j4*4+3] = __expf(t3);
            sum += e[j4*4+0] + e[j4*4+1] + e[j4*4+2] + e[j4*4+3];
        }
        int h = hbase + g;
        float v = v_in[(size_t)(row0 + r) * 1024 + 512 + h];
        int kk = (int)(v * 16.f); kk = kk < 0 ? 0 : (kk > 15 ? 15 : kk);
        float pref = 0.f, pk = 0.f;
#pragma unroll
        for (int j = 0; j < 16; ++j) {
            if (j < kk)  pref += e[j];
            if (j == kk) pk = e[j];
        }
        float inv   = __fdividef(1.f, sum);
        float p_k   = pk * inv;
        float ylo   = pref * inv;
        float alpha = v * 16.f - (float)kk;
        dout[(size_t)(row0 + r) * 1024 + 512 + h] = ylo + alpha * p_k;
        red[r * 8 + g] = __logf(p_k);
    }
    __syncthreads();
    if (tid < 128) {
        float s = 0.f;
#pragma unroll
        for (int g = 0; g < 8; ++g) s += red[tid * 8 + g];
        g_ldp[(size_t)(row0 + tid) * NT2 + blockIdx.x] = s;
    }
}

// ---------------- prep + finalize -------------------------------------------
__global__ __launch_bounds__(256) void k_prep_a1(const float* __restrict__ v_in,
                                                 float* __restrict__ out)
{
    int i = blockIdx.x * 256 + threadIdx.x;          // float4 over [BQ,128]
    if (i >= BQ * 128) return;
    int row = i >> 7, c4 = i & 127;
    float4 v = ((const float4*)v_in)[(size_t)row * 256 + c4];
    ((float4*)out)[(size_t)row * 256 + c4] = v;       // passive copy
    float a[4] = {v.x - 0.5f, v.y - 0.5f, v.z - 0.5f, v.w - 0.5f};
    __nv_bfloat162 h2[2], l2[2];
#pragma unroll
    for (int p = 0; p < 2; ++p) {
        __nv_bfloat16 h0 = __float2bfloat16(a[2*p]), h1 = __float2bfloat16(a[2*p+1]);
        h2[p].x = h0; h2[p].y = h1;
        l2[p].x = __float2bfloat16(a[2*p]   - __bfloat162float(h0));
        l2[p].y = __float2bfloat16(a[2*p+1] - __bfloat162float(h1));
    }
    __nv_bfloat162* ph = (__nv_bfloat162*)&g_a1h[(size_t)row * HDIM + c4 * 4];
    __nv_bfloat162* pl = (__nv_bfloat162*)&g_a1l[(size_t)row * HDIM + c4 * 4];
    ph[0] = h2[0]; ph[1] = h2[1];
    pl[0] = l2[0]; pl[1] = l2[1];
}

__device__ __forceinline__ void prep_wt_body(
    const float* __restrict__ W, __nv_bfloat16* th, __nv_bfloat16* tl, int N)
{
    __shared__ float t[32][33];
    int n0 = blockIdx.x * 32, k0 = blockIdx.y * 32;
    int tx = threadIdx.x, ty = threadIdx.y;
#pragma unroll
    for (int i = 0; i < 4; ++i)
        t[ty + 8 * i][tx] = W[(size_t)(k0 + ty + 8 * i) * N + n0 + tx];
    __syncthreads();
#pragma unroll
    for (int i = 0; i < 4; ++i) {
        float v = t[tx][ty + 8 * i];
        __nv_bfloat16 hi = __float2bfloat16(v);
        th[(size_t)(n0 + ty + 8 * i) * HDIM + k0 + tx] = hi;
        tl[(size_t)(n0 + ty + 8 * i) * HDIM + k0 + tx] =
            __float2bfloat16(v - __bfloat162float(hi));
    }
}
__global__ void k_prep_w1(const float* __restrict__ W){ prep_wt_body(W, g_w1h, g_w1l, HDIM); }
__global__ void k_prep_w2(const float* __restrict__ W){ prep_wt_body(W, g_w2h, g_w2l, HK);   }

__global__ __launch_bounds__(256) void k_finalize(const float* __restrict__ logd,
                                                  float* __restrict__ dout)
{
    int b = blockIdx.x * 256 + threadIdx.x;
    if (b < BQ) {
        float s = 0.f;
        const float4* p = (const float4*)&g_ldp[(size_t)b * NT2];
#pragma unroll
        for (int i = 0; i < NT2 / 4; ++i) {
            float4 v = p[i];
            s += v.x + v.y + v.z + v.w;
        }
        dout[(size_t)BQ * 1024 + b] = logd[b] - s;
    }
}

// ---------------- launch -----------------------------------------------------
extern "C" void kernel_launch(void* const* d_in, const int* in_sizes, int n_in,
                              void* d_out, int out_size)
{
    const float* v_in = (const float*)d_in[0];
    const float* logd = (const float*)d_in[1];
    const float* W1   = (const float*)d_in[2];
    const float* b1   = (const float*)d_in[3];
    const float* W2   = (const float*)d_in[4];
    const float* b2   = (const float*)d_in[5];
    float* out = (float*)d_out;

    cudaFuncSetAttribute(k_gemm1_tc, cudaFuncAttributeMaxDynamicSharedMemorySize, DYNSMEM);
    cudaFuncSetAttribute(k_gemm2_tc, cudaFuncAttributeMaxDynamicSharedMemorySize, DYNSMEM);

    k_prep_a1<<<(BQ * 128 + 255) / 256, 256>>>(v_in, out);
    k_prep_w1<<<dim3(16, 16),  dim3(32, 8)>>>(W1);
    k_prep_w2<<<dim3(256, 16), dim3(32, 8)>>>(W2);
    k_gemm1_tc<<<dim3(4, 64),  256, DYNSMEM>>>(b1);
    k_gemm2_tc<<<dim3(64, 64), 256, DYNSMEM>>>(v_in, b2, out);
    k_finalize<<<32, 256>>>(logd, out);
}